// round 13
// baseline (speedup 1.0000x reference)
#include <cuda_runtime.h>
#include <cuda_fp16.h>
#include <mma.h>
#include <cstdint>
#include <math.h>
using namespace nvcuda;

#define BB 4096
#define PP 16
#define DD 512
#define FF 2048
#define EE 8
#define MAXTILES 1032
#define MAXSLOTS (MAXTILES * 8)

// ---------------- device scratch (no runtime allocation) ----------------
__device__ int    g_counts[EE];
__device__ int    g_rows[EE * BB];
__device__ float  g_gates[EE * BB];
__device__ int    g_total;
__device__ int    g_binc[BB];
__device__ int    g_inv[BB * 2];
__device__ int    g_srow[MAXSLOTS];
__device__ float  g_sgate[MAXSLOTS];
__device__ int    g_texp[MAXTILES];
__device__ __half g_W1h[(size_t)EE * DD * FF];   // [e][d][f]
__device__ __half g_W2h[(size_t)EE * FF * DD];   // [e][f][d]
__device__ __half g_Xg[(size_t)MAXSLOTS * PP * DD];
__device__ __half g_H [(size_t)MAXSLOTS * PP * FF];
__device__ __half g_Yh[(size_t)MAXSLOTS * PP * DD];   // fp16 gated outputs

// ---------------- helpers ----------------
__device__ __forceinline__ uint32_t smem_u32(const void* p) {
    uint32_t a;
    asm("{ .reg .u64 t; cvta.to.shared.u64 t, %1; cvt.u32.u64 %0, t; }" : "=r"(a) : "l"(p));
    return a;
}
__device__ __forceinline__ void cp16(uint32_t dst, const void* src) {
    asm volatile("cp.async.cg.shared.global [%0], [%1], 16;" :: "r"(dst), "l"(src));
}
#define CP_COMMIT() asm volatile("cp.async.commit_group;" ::: "memory")
#define CP_WAIT(n)  asm volatile("cp.async.wait_group %0;" :: "n"(n) : "memory")

__device__ __forceinline__ float gelu_t(float t) {
    float c = t * (1.0f + 0.044715f * t * t);
    float th;
    asm("tanh.approx.f32 %0, %1;" : "=f"(th) : "f"(0.7978845608028654f * c));
    return 0.5f * t * (1.0f + th);
}

// ---------------- small kernels ----------------
__global__ void zero_kernel() {
    int i = blockIdx.x * 256 + threadIdx.x;
    if (i < EE) g_counts[i] = 0;
    if (i < BB) g_binc[i] = 0;
}

__global__ void router_kernel(const float* __restrict__ aff,
                              const float* __restrict__ noise) {
    int b = blockIdx.x * blockDim.x + threadIdx.x;
    if (b >= BB) return;
    float v[EE];
#pragma unroll
    for (int e = 0; e < EE; ++e) {
        float a  = aff[b * EE + e];
        float sp = (a > 0.f) ? (a + log1pf(expf(-a))) : log1pf(expf(a));
        v[e] = a + noise[b * EE + e] * sp;
    }
    int i0 = 0; float v0 = v[0];
#pragma unroll
    for (int e = 1; e < EE; ++e) if (v[e] > v0) { v0 = v[e]; i0 = e; }
    int i1 = -1; float v1 = -INFINITY;
#pragma unroll
    for (int e = 0; e < EE; ++e) if (e != i0 && v[e] > v1) { v1 = v[e]; i1 = e; }
    float ex  = expf(v1 - v0);
    float inv = 1.f / (1.f + ex);
    int p0 = atomicAdd(&g_counts[i0], 1);
    g_rows[i0 * BB + p0]  = b;
    g_gates[i0 * BB + p0] = inv;
    int p1 = atomicAdd(&g_counts[i1], 1);
    g_rows[i1 * BB + p1]  = b;
    g_gates[i1 * BB + p1] = ex * inv;
}

// per-expert scatter to padded slots; offsets via in-block 8-element prefix
__global__ void schedule_kernel() {
    int e = blockIdx.x;
    int off = 0, total = 0;
#pragma unroll
    for (int i = 0; i < EE; ++i) {
        int c = (g_counts[i] + 7) & ~7;
        if (i < e) off += c;
        total += c;
    }
    if (e == 0 && threadIdx.x == 0) g_total = total;
    int cnt = g_counts[e];
    int pad = (cnt + 7) & ~7;
    for (int j = threadIdx.x; j < pad; j += 256) {
        int slot = off + j;
        if (j < cnt) {
            int b = g_rows[e * BB + j];
            g_srow[slot]  = b;
            g_sgate[slot] = g_gates[e * BB + j];
            int pos = atomicAdd(&g_binc[b], 1);
            g_inv[b * 2 + pos] = slot;
        } else {
            g_srow[slot]  = g_rows[e * BB];
            g_sgate[slot] = 0.f;
        }
    }
    for (int t = threadIdx.x; t < pad / 8; t += 256) g_texp[off / 8 + t] = e;
}

__global__ void convw_kernel(const float* __restrict__ W1, const float* __restrict__ W2) {
    size_t n   = (size_t)EE * DD * FF;
    size_t idx = ((size_t)blockIdx.x * 256 + threadIdx.x) * 4;
    if (idx < n) {
        float4 v = *(const float4*)(W1 + idx);
        g_W1h[idx + 0] = __float2half_rn(v.x); g_W1h[idx + 1] = __float2half_rn(v.y);
        g_W1h[idx + 2] = __float2half_rn(v.z); g_W1h[idx + 3] = __float2half_rn(v.w);
    } else {
        size_t j = idx - n;
        if (j >= n) return;
        float4 v = *(const float4*)(W2 + j);
        g_W2h[j + 0] = __float2half_rn(v.x); g_W2h[j + 1] = __float2half_rn(v.y);
        g_W2h[j + 2] = __float2half_rn(v.z); g_W2h[j + 3] = __float2half_rn(v.w);
    }
}

__global__ void gather_kernel(const float* __restrict__ X) {
    int slot = blockIdx.x;
    if (slot >= g_total) return;
    int b = g_srow[slot];
    const float4* src = (const float4*)(X + (size_t)b * PP * DD);
    __half2* dst = (__half2*)(g_Xg + (size_t)slot * PP * DD);
    for (int i = threadIdx.x; i < PP * DD / 4; i += 256) {
        float4 v = src[i];
        dst[i * 2 + 0] = __floats2half2_rn(v.x, v.y);
        dst[i * 2 + 1] = __floats2half2_rn(v.z, v.w);
    }
}

// ---------------- fused GEMM: per tile, pass1 (H) then pass2 (Y) ----------------
// phase1 smem: A[128][520]h = 133120 | B[2][64][136]h = 34816 @133120 | C[128][68]f @167936
// phase2 smem: A[2][128][72]h = 36864 @0 | B[2][64][136]h @36864 | C[128][68]f @71680
#define LDA1 520
#define LDB  136
#define LDC  68
#define LDA2 72
#define SM1_B 133120
#define SM1_C 167936
#define SM2_B 36864
#define SM2_C 71680
#define SMF_BYTES 202752

__global__ __launch_bounds__(256)
void gemm_fused(const float* __restrict__ bias1, const float* __restrict__ bias2) {
    int tile = blockIdx.x;
    if (tile * 8 >= g_total) return;
    int e = g_texp[tile];

    extern __shared__ char sm[];
    int tid = threadIdx.x, wid = tid >> 5;
    int wm = (wid >> 1) * 32, wn = (wid & 1) * 64;

    // ================= phase 1: H = gelu(X @ W1 + b1) =================
    {
        half*  A  = (half*)sm;
        half*  Bs = (half*)(sm + SM1_B);
        float* C  = (float*)(sm + SM1_C);
        uint32_t sA = smem_u32(A), sB = smem_u32(Bs);

        const half* Ag = g_Xg + (size_t)tile * 128 * DD;
        const half* Bg = g_W1h + (size_t)e * DD * FF;
        const float* be = bias1 + e * FF;

        // resident A: 128x512 fp16 = 8192 16B chunks
#pragma unroll
        for (int i = 0; i < 32; ++i) {
            int idx = i * 256 + tid;
            int r = idx >> 6, c = (idx & 63) << 3;
            cp16(sA + (uint32_t)(r * LDA1 + c) * 2, Ag + r * DD + c);
        }

        auto stageB = [&](int q) {
            uint32_t dst = sB + (uint32_t)(q & 1) * (64 * LDB * 2);
            int nb = (q >> 3) << 7, k0 = (q & 7) << 6;
#pragma unroll
            for (int i = 0; i < 4; ++i) {
                int idx = i * 256 + tid;
                int r = idx >> 4, c = (idx & 15) << 3;
                cp16(dst + (uint32_t)(r * LDB + c) * 2, Bg + (size_t)(k0 + r) * FF + nb + c);
            }
        };
        stageB(0);
        CP_COMMIT();

        wmma::fragment<wmma::accumulator, 16, 16, 16, float> acc[2][4];

        for (int q = 0; q < 128; ++q) {
            int kc = q & 7;
            if (kc == 0) {
#pragma unroll
                for (int i = 0; i < 2; ++i)
#pragma unroll
                    for (int j = 0; j < 4; ++j) wmma::fill_fragment(acc[i][j], 0.f);
            }
            if (q + 1 < 128) { stageB(q + 1); CP_COMMIT(); CP_WAIT(1); }
            else             { CP_WAIT(0); }
            __syncthreads();

            half* Bq = Bs + (q & 1) * (64 * LDB);
            int k0 = kc << 6;
#pragma unroll
            for (int kk = 0; kk < 64; kk += 16) {
                wmma::fragment<wmma::matrix_a, 16, 16, 16, half, wmma::row_major> af[2];
                wmma::fragment<wmma::matrix_b, 16, 16, 16, half, wmma::row_major> bf[4];
                wmma::load_matrix_sync(af[0], A + (wm +  0) * LDA1 + k0 + kk, LDA1);
                wmma::load_matrix_sync(af[1], A + (wm + 16) * LDA1 + k0 + kk, LDA1);
#pragma unroll
                for (int j = 0; j < 4; ++j)
                    wmma::load_matrix_sync(bf[j], Bq + kk * LDB + wn + 16 * j, LDB);
#pragma unroll
                for (int i = 0; i < 2; ++i)
#pragma unroll
                    for (int j = 0; j < 4; ++j) wmma::mma_sync(acc[i][j], af[i], bf[j], acc[i][j]);
            }
            __syncthreads();

            if (kc == 7) {
                int nb = (q >> 3) << 7;
#pragma unroll
                for (int p = 0; p < 2; ++p) {
                    if ((wid & 1) == p) {
#pragma unroll
                        for (int i = 0; i < 2; ++i)
#pragma unroll
                            for (int j = 0; j < 4; ++j)
                                wmma::store_matrix_sync(C + (wm + 16 * i) * LDC + 16 * j,
                                                        acc[i][j], LDC, wmma::mem_row_major);
                    }
                    __syncthreads();
                    for (int i = tid; i < 128 * 64; i += 256) {
                        int m = i >> 6, n = i & 63;
                        float t = C[m * LDC + n] + be[nb + p * 64 + n];
                        g_H[(size_t)(tile * 128 + m) * FF + nb + p * 64 + n] =
                            __float2half_rn(gelu_t(t));
                    }
                    __syncthreads();
                }
            }
        }
    }
    __syncthreads();   // H of this tile visible CTA-wide (STG -> L2; cp.async.cg reads L2)

    // ================= phase 2: Y = gate*(H @ W2 + b2), fp16 out =================
    {
        half*  As = (half*)sm;
        half*  Bs = (half*)(sm + SM2_B);
        float* C  = (float*)(sm + SM2_C);
        uint32_t sA = smem_u32(As), sB = smem_u32(Bs);

        const half* Ag = g_H  + (size_t)tile * 128 * FF;
        const half* Bg = g_W2h + (size_t)e * FF * DD;
        const float* be = bias2 + e * DD;

        for (int nbi = 0; nbi < 4; ++nbi) {
            int nb = nbi << 7;

            auto stage = [&](int q) {
                int k0 = q << 6, buf = q & 1;
                uint32_t da = sA + (uint32_t)buf * (128 * LDA2 * 2);
                uint32_t db = sB + (uint32_t)buf * (64 * LDB * 2);
#pragma unroll
                for (int i = 0; i < 4; ++i) {
                    int idx = i * 256 + tid;
                    int r = idx >> 3, c = (idx & 7) << 3;
                    cp16(da + (uint32_t)(r * LDA2 + c) * 2, Ag + (size_t)r * FF + k0 + c);
                }
#pragma unroll
                for (int i = 0; i < 4; ++i) {
                    int idx = i * 256 + tid;
                    int r = idx >> 4, c = (idx & 15) << 3;
                    cp16(db + (uint32_t)(r * LDB + c) * 2, Bg + (size_t)(k0 + r) * DD + nb + c);
                }
            };
            stage(0);
            CP_COMMIT();

            wmma::fragment<wmma::accumulator, 16, 16, 16, float> acc[2][4];
#pragma unroll
            for (int i = 0; i < 2; ++i)
#pragma unroll
                for (int j = 0; j < 4; ++j) wmma::fill_fragment(acc[i][j], 0.f);

            for (int q = 0; q < 32; ++q) {
                if (q + 1 < 32) { stage(q + 1); CP_COMMIT(); CP_WAIT(1); }
                else            { CP_WAIT(0); }
                __syncthreads();

                half* Aq = As + (q & 1) * (128 * LDA2);
                half* Bq = Bs + (q & 1) * (64 * LDB);
#pragma unroll
                for (int kk = 0; kk < 64; kk += 16) {
                    wmma::fragment<wmma::matrix_a, 16, 16, 16, half, wmma::row_major> af[2];
                    wmma::fragment<wmma::matrix_b, 16, 16, 16, half, wmma::row_major> bf[4];
                    wmma::load_matrix_sync(af[0], Aq + (wm +  0) * LDA2 + kk, LDA2);
                    wmma::load_matrix_sync(af[1], Aq + (wm + 16) * LDA2 + kk, LDA2);
#pragma unroll
                    for (int j = 0; j < 4; ++j)
                        wmma::load_matrix_sync(bf[j], Bq + kk * LDB + wn + 16 * j, LDB);
#pragma unroll
                    for (int i = 0; i < 2; ++i)
#pragma unroll
                        for (int j = 0; j < 4; ++j) wmma::mma_sync(acc[i][j], af[i], bf[j], acc[i][j]);
                }
                __syncthreads();
            }

#pragma unroll
            for (int p = 0; p < 2; ++p) {
                if ((wid & 1) == p) {
#pragma unroll
                    for (int i = 0; i < 2; ++i)
#pragma unroll
                        for (int j = 0; j < 4; ++j)
                            wmma::store_matrix_sync(C + (wm + 16 * i) * LDC + 16 * j,
                                                    acc[i][j], LDC, wmma::mem_row_major);
                }
                __syncthreads();
                for (int i = tid; i < 128 * 32; i += 256) {
                    int m = i >> 5, n = (i & 31) * 2;
                    int slot = tile * 8 + (m >> 4);
                    float gt = g_sgate[slot];
                    float y0 = (C[m * LDC + n]     + be[nb + p * 64 + n])     * gt;
                    float y1 = (C[m * LDC + n + 1] + be[nb + p * 64 + n + 1]) * gt;
                    *(__half2*)(g_Yh + (size_t)(tile * 128 + m) * DD + nb + p * 64 + n) =
                        __floats2half2_rn(y0, y1);
                }
                __syncthreads();
            }
        }
    }
}

// out[b] = Y[slot0(b)] + Y[slot1(b)]  (fp16 reads, fp32 sum; commutative)
__global__ void combine_kernel(float* __restrict__ out) {
    int b  = blockIdx.x;
    int s0 = g_inv[2 * b], s1 = g_inv[2 * b + 1];
    const uint4* y0 = (const uint4*)(g_Yh + (size_t)s0 * PP * DD);
    const uint4* y1 = (const uint4*)(g_Yh + (size_t)s1 * PP * DD);
    float4* o = (float4*)(out + (size_t)b * PP * DD);
    for (int i = threadIdx.x; i < PP * DD / 8; i += 256) {
        uint4 a = y0[i], c = y1[i];
#pragma unroll
        for (int j = 0; j < 4; ++j) {
            __half2 ha = *(__half2*)&((&a.x)[j]);
            __half2 hc = *(__half2*)&((&c.x)[j]);
            float2 fa = __half22float2(ha), fc = __half22float2(hc);
            o[i * 2 + (j >> 1)].x = 0;  // placeholder overwritten below
        }
        // unpack into two float4 stores
        __half2 a0 = *(__half2*)&a.x, a1 = *(__half2*)&a.y, a2 = *(__half2*)&a.z, a3 = *(__half2*)&a.w;
        __half2 c0 = *(__half2*)&c.x, c1 = *(__half2*)&c.y, c2 = *(__half2*)&c.z, c3 = *(__half2*)&c.w;
        float2 f0 = __half22float2(a0), g0 = __half22float2(c0);
        float2 f1 = __half22float2(a1), g1 = __half22float2(c1);
        float2 f2 = __half22float2(a2), g2 = __half22float2(c2);
        float2 f3 = __half22float2(a3), g3 = __half22float2(c3);
        o[i * 2 + 0] = make_float4(f0.x + g0.x, f0.y + g0.y, f1.x + g1.x, f1.y + g1.y);
        o[i * 2 + 1] = make_float4(f2.x + g2.x, f2.y + g2.y, f3.x + g3.x, f3.y + g3.y);
    }
}

// ---------------- launch ----------------
extern "C" void kernel_launch(void* const* d_in, const int* in_sizes, int n_in,
                              void* d_out, int out_size) {
    const float* patch_x  = (const float*)d_in[0];
    const float* affinity = (const float*)d_in[2];
    const float* noise    = (const float*)d_in[3];
    const float* W1       = (const float*)d_in[4];
    const float* b1       = (const float*)d_in[5];
    const float* W2       = (const float*)d_in[6];
    const float* b2       = (const float*)d_in[7];
    float* out = (float*)d_out;

    zero_kernel<<<16, 256>>>();
    router_kernel<<<BB / 256, 256>>>(affinity, noise);
    schedule_kernel<<<EE, 256>>>();

    size_t wn = (size_t)EE * DD * FF;
    int convBlocks = (int)((2 * wn / 4 + 255) / 256);
    convw_kernel<<<convBlocks, 256>>>(W1, W2);
    gather_kernel<<<MAXSLOTS, 256>>>(patch_x);

    cudaFuncSetAttribute(gemm_fused,
                         cudaFuncAttributeMaxDynamicSharedMemorySize, SMF_BYTES);
    gemm_fused<<<MAXTILES, 256, SMF_BYTES>>>(b1, b2);

    combine_kernel<<<BB, 256>>>(out);
}

// round 14
// speedup vs baseline: 1.0951x; 1.0951x over previous
#include <cuda_runtime.h>
#include <cuda_fp16.h>
#include <mma.h>
#include <cstdint>
#include <math.h>
using namespace nvcuda;

#define BB 4096
#define PP 16
#define DD 512
#define FF 2048
#define EE 8
#define MAXTILES 1032
#define MAXSLOTS (MAXTILES * 8)

// ---------------- device scratch (no runtime allocation) ----------------
__device__ int    g_counts[EE];
__device__ int    g_rows[EE * BB];
__device__ float  g_gates[EE * BB];
__device__ int    g_total;
__device__ int    g_binc[BB];
__device__ int    g_inv[BB * 2];
__device__ int    g_srow[MAXSLOTS];
__device__ float  g_sgate[MAXSLOTS];
__device__ int    g_texp[MAXTILES];
__device__ __half g_W1h[(size_t)EE * DD * FF];   // [e][d][f]
__device__ __half g_W2h[(size_t)EE * FF * DD];   // [e][f][d]
__device__ __half g_H [(size_t)MAXSLOTS * PP * FF];
__device__ __half g_Yh[(size_t)MAXSLOTS * PP * DD];   // fp16 gated outputs

// ---------------- helpers ----------------
__device__ __forceinline__ uint32_t smem_u32(const void* p) {
    uint32_t a;
    asm("{ .reg .u64 t; cvta.to.shared.u64 t, %1; cvt.u32.u64 %0, t; }" : "=r"(a) : "l"(p));
    return a;
}
__device__ __forceinline__ void cp16(uint32_t dst, const void* src) {
    asm volatile("cp.async.cg.shared.global [%0], [%1], 16;" :: "r"(dst), "l"(src));
}
#define CP_COMMIT() asm volatile("cp.async.commit_group;" ::: "memory")
#define CP_WAIT(n)  asm volatile("cp.async.wait_group %0;" :: "n"(n) : "memory")

__device__ __forceinline__ float gelu_t(float t) {
    float c = t * (1.0f + 0.044715f * t * t);
    float th;
    asm("tanh.approx.f32 %0, %1;" : "=f"(th) : "f"(0.7978845608028654f * c));
    return 0.5f * t * (1.0f + th);
}

// ---------------- small kernels ----------------
__global__ void zero_kernel() {
    int i = blockIdx.x * 256 + threadIdx.x;
    if (i < EE) g_counts[i] = 0;
    if (i < BB) g_binc[i] = 0;
}

__global__ void router_kernel(const float* __restrict__ aff,
                              const float* __restrict__ noise) {
    int b = blockIdx.x * blockDim.x + threadIdx.x;
    if (b >= BB) return;
    float v[EE];
#pragma unroll
    for (int e = 0; e < EE; ++e) {
        float a  = aff[b * EE + e];
        float sp = (a > 0.f) ? (a + log1pf(expf(-a))) : log1pf(expf(a));
        v[e] = a + noise[b * EE + e] * sp;
    }
    int i0 = 0; float v0 = v[0];
#pragma unroll
    for (int e = 1; e < EE; ++e) if (v[e] > v0) { v0 = v[e]; i0 = e; }
    int i1 = -1; float v1 = -INFINITY;
#pragma unroll
    for (int e = 0; e < EE; ++e) if (e != i0 && v[e] > v1) { v1 = v[e]; i1 = e; }
    float ex  = expf(v1 - v0);
    float inv = 1.f / (1.f + ex);
    int p0 = atomicAdd(&g_counts[i0], 1);
    g_rows[i0 * BB + p0]  = b;
    g_gates[i0 * BB + p0] = inv;
    int p1 = atomicAdd(&g_counts[i1], 1);
    g_rows[i1 * BB + p1]  = b;
    g_gates[i1 * BB + p1] = ex * inv;
}

// per-expert scatter to padded slots; offsets via in-block 8-element prefix
__global__ void schedule_kernel() {
    int e = blockIdx.x;
    int off = 0, total = 0;
#pragma unroll
    for (int i = 0; i < EE; ++i) {
        int c = (g_counts[i] + 7) & ~7;
        if (i < e) off += c;
        total += c;
    }
    if (e == 0 && threadIdx.x == 0) g_total = total;
    int cnt = g_counts[e];
    int pad = (cnt + 7) & ~7;
    for (int j = threadIdx.x; j < pad; j += 256) {
        int slot = off + j;
        if (j < cnt) {
            int b = g_rows[e * BB + j];
            g_srow[slot]  = b;
            g_sgate[slot] = g_gates[e * BB + j];
            int pos = atomicAdd(&g_binc[b], 1);
            g_inv[b * 2 + pos] = slot;
        } else {
            g_srow[slot]  = g_rows[e * BB];
            g_sgate[slot] = 0.f;
        }
    }
    for (int t = threadIdx.x; t < pad / 8; t += 256) g_texp[off / 8 + t] = e;
}

__global__ void convw_kernel(const float* __restrict__ W1, const float* __restrict__ W2) {
    size_t n   = (size_t)EE * DD * FF;
    size_t idx = ((size_t)blockIdx.x * 256 + threadIdx.x) * 4;
    if (idx < n) {
        float4 v = *(const float4*)(W1 + idx);
        g_W1h[idx + 0] = __float2half_rn(v.x); g_W1h[idx + 1] = __float2half_rn(v.y);
        g_W1h[idx + 2] = __float2half_rn(v.z); g_W1h[idx + 3] = __float2half_rn(v.w);
    } else {
        size_t j = idx - n;
        if (j >= n) return;
        float4 v = *(const float4*)(W2 + j);
        g_W2h[j + 0] = __float2half_rn(v.x); g_W2h[j + 1] = __float2half_rn(v.y);
        g_W2h[j + 2] = __float2half_rn(v.z); g_W2h[j + 3] = __float2half_rn(v.w);
    }
}

// ---------------- GEMM pass 1: H = gelu(X @ W1 + b1), A-resident ----------------
// A gathered+converted in-kernel from fp32 X (no separate gather pass).
// smem: A[128][520]h = 133120 B | B[2][64][136]h = 34816 B | C[128][68]f = 34816 B
#define LDA1 520
#define LDB  136
#define LDC  68
#define SM1_B 133120
#define SM1_C 167936
#define SM1_BYTES 202752

__global__ __launch_bounds__(256)
void gemm1_kernel(const float* __restrict__ X, const float* __restrict__ bias) {
    int tile = blockIdx.x;
    if (tile * 8 >= g_total) return;
    int e = g_texp[tile];

    extern __shared__ char sm[];
    half*  A  = (half*)sm;
    half*  Bs = (half*)(sm + SM1_B);
    float* C  = (float*)(sm + SM1_C);
    uint32_t sB = smem_u32(Bs);

    const half* Bg = g_W1h + (size_t)e * DD * FF;
    const float* be = bias + e * FF;

    int tid = threadIdx.x, wid = tid >> 5;
    int wm = (wid >> 1) * 32, wn = (wid & 1) * 64;

    // B chunk q staged via cp.async (kick off chunk 0 before the A gather)
    auto stageB = [&](int q) {
        uint32_t dst = sB + (uint32_t)(q & 1) * (64 * LDB * 2);
        int nb = (q >> 3) << 7, k0 = (q & 7) << 6;
#pragma unroll
        for (int i = 0; i < 4; ++i) {
            int idx = i * 256 + tid;
            int r = idx >> 4, c = (idx & 15) << 3;
            cp16(dst + (uint32_t)(r * LDB + c) * 2, Bg + (size_t)(k0 + r) * FF + nb + c);
        }
    };
    stageB(0);
    CP_COMMIT();

    // gather + convert A: row r -> slot tile*8+(r>>4), patch r&15; 8 halves per step
    {
        int r0 = tid >> 1;                    // 0..127, two threads per row
        int half_sel = tid & 1;               // cols [0,256) or [256,512)
#pragma unroll
        for (int rr = 0; rr < 128; rr += 128) {}   // (keep structure simple)
        int slot = tile * 8 + (r0 >> 4);
        int b = g_srow[slot];
        const float4* src = (const float4*)(X + ((size_t)b * PP + (r0 & 15)) * DD + half_sel * 256);
        uint4* dstA = (uint4*)(A + r0 * LDA1 + half_sel * 256);
#pragma unroll
        for (int i = 0; i < 32; ++i) {        // 32 x 8 floats = 256 cols
            float4 v0 = src[i * 2 + 0];
            float4 v1 = src[i * 2 + 1];
            __half2 h0 = __floats2half2_rn(v0.x, v0.y);
            __half2 h1 = __floats2half2_rn(v0.z, v0.w);
            __half2 h2 = __floats2half2_rn(v1.x, v1.y);
            __half2 h3 = __floats2half2_rn(v1.z, v1.w);
            dstA[i] = make_uint4(*(uint32_t*)&h0, *(uint32_t*)&h1,
                                 *(uint32_t*)&h2, *(uint32_t*)&h3);
        }
    }

    wmma::fragment<wmma::accumulator, 16, 16, 16, float> acc[2][4];

    for (int q = 0; q < 128; ++q) {
        int kc = q & 7;
        if (kc == 0) {
#pragma unroll
            for (int i = 0; i < 2; ++i)
#pragma unroll
                for (int j = 0; j < 4; ++j) wmma::fill_fragment(acc[i][j], 0.f);
        }
        if (q + 1 < 128) { stageB(q + 1); CP_COMMIT(); CP_WAIT(1); }
        else             { CP_WAIT(0); }
        __syncthreads();   // also orders the A gather (STS) on first iteration

        half* Bq = Bs + (q & 1) * (64 * LDB);
        int k0 = kc << 6;
#pragma unroll
        for (int kk = 0; kk < 64; kk += 16) {
            wmma::fragment<wmma::matrix_a, 16, 16, 16, half, wmma::row_major> af[2];
            wmma::fragment<wmma::matrix_b, 16, 16, 16, half, wmma::row_major> bf[4];
            wmma::load_matrix_sync(af[0], A + (wm +  0) * LDA1 + k0 + kk, LDA1);
            wmma::load_matrix_sync(af[1], A + (wm + 16) * LDA1 + k0 + kk, LDA1);
#pragma unroll
            for (int j = 0; j < 4; ++j)
                wmma::load_matrix_sync(bf[j], Bq + kk * LDB + wn + 16 * j, LDB);
#pragma unroll
            for (int i = 0; i < 2; ++i)
#pragma unroll
                for (int j = 0; j < 4; ++j) wmma::mma_sync(acc[i][j], af[i], bf[j], acc[i][j]);
        }
        __syncthreads();   // compute done before next iter's stage overwrites B buf

        if (kc == 7) {
            int nb = (q >> 3) << 7;
#pragma unroll
            for (int p = 0; p < 2; ++p) {   // two N=64 phases through C
                if ((wid & 1) == p) {
#pragma unroll
                    for (int i = 0; i < 2; ++i)
#pragma unroll
                        for (int j = 0; j < 4; ++j)
                            wmma::store_matrix_sync(C + (wm + 16 * i) * LDC + 16 * j,
                                                    acc[i][j], LDC, wmma::mem_row_major);
                }
                __syncthreads();
                for (int i = tid; i < 128 * 64; i += 256) {
                    int m = i >> 6, n = i & 63;
                    float t = C[m * LDC + n] + be[nb + p * 64 + n];
                    g_H[(size_t)(tile * 128 + m) * FF + nb + p * 64 + n] =
                        __float2half_rn(gelu_t(t));
                }
                __syncthreads();
            }
        }
    }
}

// ---------------- GEMM pass 2: Y = gate*(H @ W2 + b2), fp16 out ----------------
// smem: A[2][128][72]h = 36864 B | B[2][64][136]h = 34816 B | C[128][68]f = 34816 B
#define LDA2 72
#define SM2_B 36864
#define SM2_C 71680
#define SM2_BYTES 106496

__global__ __launch_bounds__(256)
void gemm2_kernel(const float* __restrict__ bias) {
    int tile = blockIdx.y;                 // tile in y; 4 N-chunk CTAs x-adjacent
    if (tile * 8 >= g_total) return;
    int e  = g_texp[tile];
    int nb = blockIdx.x << 7;

    extern __shared__ char sm[];
    half*  As = (half*)sm;
    half*  Bs = (half*)(sm + SM2_B);
    float* C  = (float*)(sm + SM2_C);
    uint32_t sA = smem_u32(As), sB = smem_u32(Bs);

    const half* Ag = g_H  + (size_t)tile * 128 * FF;
    const half* Bg = g_W2h + (size_t)e * FF * DD;
    const float* be = bias + e * DD;

    int tid = threadIdx.x, wid = tid >> 5;
    int wm = (wid >> 1) * 32, wn = (wid & 1) * 64;

    auto stage = [&](int q) {
        int k0 = q << 6, buf = q & 1;
        uint32_t da = sA + (uint32_t)buf * (128 * LDA2 * 2);
        uint32_t db = sB + (uint32_t)buf * (64 * LDB * 2);
#pragma unroll
        for (int i = 0; i < 4; ++i) {
            int idx = i * 256 + tid;
            int r = idx >> 3, c = (idx & 7) << 3;
            cp16(da + (uint32_t)(r * LDA2 + c) * 2, Ag + (size_t)r * FF + k0 + c);
        }
#pragma unroll
        for (int i = 0; i < 4; ++i) {
            int idx = i * 256 + tid;
            int r = idx >> 4, c = (idx & 15) << 3;
            cp16(db + (uint32_t)(r * LDB + c) * 2, Bg + (size_t)(k0 + r) * DD + nb + c);
        }
    };
    stage(0);
    CP_COMMIT();

    wmma::fragment<wmma::accumulator, 16, 16, 16, float> acc[2][4];
#pragma unroll
    for (int i = 0; i < 2; ++i)
#pragma unroll
        for (int j = 0; j < 4; ++j) wmma::fill_fragment(acc[i][j], 0.f);

    for (int q = 0; q < 32; ++q) {
        if (q + 1 < 32) { stage(q + 1); CP_COMMIT(); CP_WAIT(1); }
        else            { CP_WAIT(0); }
        __syncthreads();

        half* Aq = As + (q & 1) * (128 * LDA2);
        half* Bq = Bs + (q & 1) * (64 * LDB);
#pragma unroll
        for (int kk = 0; kk < 64; kk += 16) {
            wmma::fragment<wmma::matrix_a, 16, 16, 16, half, wmma::row_major> af[2];
            wmma::fragment<wmma::matrix_b, 16, 16, 16, half, wmma::row_major> bf[4];
            wmma::load_matrix_sync(af[0], Aq + (wm +  0) * LDA2 + kk, LDA2);
            wmma::load_matrix_sync(af[1], Aq + (wm + 16) * LDA2 + kk, LDA2);
#pragma unroll
            for (int j = 0; j < 4; ++j)
                wmma::load_matrix_sync(bf[j], Bq + kk * LDB + wn + 16 * j, LDB);
#pragma unroll
            for (int i = 0; i < 2; ++i)
#pragma unroll
                for (int j = 0; j < 4; ++j) wmma::mma_sync(acc[i][j], af[i], bf[j], acc[i][j]);
        }
        __syncthreads();
    }

#pragma unroll
    for (int p = 0; p < 2; ++p) {
        if ((wid & 1) == p) {
#pragma unroll
            for (int i = 0; i < 2; ++i)
#pragma unroll
                for (int j = 0; j < 4; ++j)
                    wmma::store_matrix_sync(C + (wm + 16 * i) * LDC + 16 * j,
                                            acc[i][j], LDC, wmma::mem_row_major);
        }
        __syncthreads();
        for (int i = tid; i < 128 * 32; i += 256) {
            int m = i >> 5, n = (i & 31) * 2;
            int slot = tile * 8 + (m >> 4);
            float gt = g_sgate[slot];
            float y0 = (C[m * LDC + n]     + be[nb + p * 64 + n])     * gt;
            float y1 = (C[m * LDC + n + 1] + be[nb + p * 64 + n + 1]) * gt;
            *(__half2*)(g_Yh + (size_t)(tile * 128 + m) * DD + nb + p * 64 + n) =
                __floats2half2_rn(y0, y1);
        }
        __syncthreads();
    }
}

// out[b] = Y[slot0(b)] + Y[slot1(b)]  (fp16 reads, fp32 sum; commutative)
__global__ void combine_kernel(float* __restrict__ out) {
    int b  = blockIdx.x;
    int s0 = g_inv[2 * b], s1 = g_inv[2 * b + 1];
    const uint4* y0 = (const uint4*)(g_Yh + (size_t)s0 * PP * DD);
    const uint4* y1 = (const uint4*)(g_Yh + (size_t)s1 * PP * DD);
    float4* o = (float4*)(out + (size_t)b * PP * DD);
    for (int i = threadIdx.x; i < PP * DD / 8; i += 256) {
        uint4 a = y0[i], c = y1[i];
        __half2 a0 = *(__half2*)&a.x, a1 = *(__half2*)&a.y, a2 = *(__half2*)&a.z, a3 = *(__half2*)&a.w;
        __half2 c0 = *(__half2*)&c.x, c1 = *(__half2*)&c.y, c2 = *(__half2*)&c.z, c3 = *(__half2*)&c.w;
        float2 f0 = __half22float2(a0), g0 = __half22float2(c0);
        float2 f1 = __half22float2(a1), g1 = __half22float2(c1);
        float2 f2 = __half22float2(a2), g2 = __half22float2(c2);
        float2 f3 = __half22float2(a3), g3 = __half22float2(c3);
        o[i * 2 + 0] = make_float4(f0.x + g0.x, f0.y + g0.y, f1.x + g1.x, f1.y + g1.y);
        o[i * 2 + 1] = make_float4(f2.x + g2.x, f2.y + g2.y, f3.x + g3.x, f3.y + g3.y);
    }
}

// ---------------- launch ----------------
extern "C" void kernel_launch(void* const* d_in, const int* in_sizes, int n_in,
                              void* d_out, int out_size) {
    const float* patch_x  = (const float*)d_in[0];
    const float* affinity = (const float*)d_in[2];
    const float* noise    = (const float*)d_in[3];
    const float* W1       = (const float*)d_in[4];
    const float* b1       = (const float*)d_in[5];
    const float* W2       = (const float*)d_in[6];
    const float* b2       = (const float*)d_in[7];
    float* out = (float*)d_out;

    zero_kernel<<<16, 256>>>();
    router_kernel<<<BB / 256, 256>>>(affinity, noise);
    schedule_kernel<<<EE, 256>>>();

    size_t wn = (size_t)EE * DD * FF;
    int convBlocks = (int)((2 * wn / 4 + 255) / 256);
    convw_kernel<<<convBlocks, 256>>>(W1, W2);

    cudaFuncSetAttribute(gemm1_kernel,
                         cudaFuncAttributeMaxDynamicSharedMemorySize, SM1_BYTES);
    cudaFuncSetAttribute(gemm2_kernel,
                         cudaFuncAttributeMaxDynamicSharedMemorySize, SM2_BYTES);

    gemm1_kernel<<<MAXTILES, 256, SM1_BYTES>>>(patch_x, b1);
    dim3 g2(DD / 128, MAXTILES);
    gemm2_kernel<<<g2, 256, SM2_BYTES>>>(b2);

    combine_kernel<<<BB, 256>>>(out);
}

// round 15
// speedup vs baseline: 1.1226x; 1.0251x over previous
#include <cuda_runtime.h>
#include <cuda_fp16.h>
#include <mma.h>
#include <cstdint>
#include <math.h>
using namespace nvcuda;

#define BB 4096
#define PP 16
#define DD 512
#define FF 2048
#define EE 8
#define MAXTILES 1032
#define MAXSLOTS (MAXTILES * 8)

// ---------------- device scratch (no runtime allocation) ----------------
__device__ int    g_counts[EE];
__device__ int    g_rows[EE * BB];
__device__ float  g_gates[EE * BB];
__device__ int    g_total;
__device__ int    g_binc[BB];
__device__ int    g_inv[BB * 2];
__device__ int    g_srow[MAXSLOTS];
__device__ float  g_sgate[MAXSLOTS];
__device__ int    g_texp[MAXTILES];
__device__ __half g_W1h[(size_t)EE * DD * FF];   // [e][d][f]
__device__ __half g_W2h[(size_t)EE * FF * DD];   // [e][f][d]
__device__ __half g_Xg[(size_t)MAXSLOTS * PP * DD];
__device__ __half g_H [(size_t)MAXSLOTS * PP * FF];
__device__ __half g_Yh[(size_t)MAXSLOTS * PP * DD];   // fp16 gated outputs

// ---------------- helpers ----------------
__device__ __forceinline__ uint32_t smem_u32(const void* p) {
    uint32_t a;
    asm("{ .reg .u64 t; cvta.to.shared.u64 t, %1; cvt.u32.u64 %0, t; }" : "=r"(a) : "l"(p));
    return a;
}
__device__ __forceinline__ void cp16(uint32_t dst, const void* src) {
    asm volatile("cp.async.cg.shared.global [%0], [%1], 16;" :: "r"(dst), "l"(src));
}
#define CP_COMMIT() asm volatile("cp.async.commit_group;" ::: "memory")
#define CP_WAIT(n)  asm volatile("cp.async.wait_group %0;" :: "n"(n) : "memory")

__device__ __forceinline__ float gelu_t(float t) {
    float c = t * (1.0f + 0.044715f * t * t);
    float th;
    asm("tanh.approx.f32 %0, %1;" : "=f"(th) : "f"(0.7978845608028654f * c));
    return 0.5f * t * (1.0f + th);
}

// ---------------- small kernels ----------------
__global__ void zero_kernel() {
    int i = blockIdx.x * 256 + threadIdx.x;
    if (i < EE) g_counts[i] = 0;
    if (i < BB) g_binc[i] = 0;
}

__global__ void router_kernel(const float* __restrict__ aff,
                              const float* __restrict__ noise) {
    int b = blockIdx.x * blockDim.x + threadIdx.x;
    if (b >= BB) return;
    float v[EE];
#pragma unroll
    for (int e = 0; e < EE; ++e) {
        float a  = aff[b * EE + e];
        float sp = (a > 0.f) ? (a + log1pf(expf(-a))) : log1pf(expf(a));
        v[e] = a + noise[b * EE + e] * sp;
    }
    int i0 = 0; float v0 = v[0];
#pragma unroll
    for (int e = 1; e < EE; ++e) if (v[e] > v0) { v0 = v[e]; i0 = e; }
    int i1 = -1; float v1 = -INFINITY;
#pragma unroll
    for (int e = 0; e < EE; ++e) if (e != i0 && v[e] > v1) { v1 = v[e]; i1 = e; }
    float ex  = expf(v1 - v0);
    float inv = 1.f / (1.f + ex);
    int p0 = atomicAdd(&g_counts[i0], 1);
    g_rows[i0 * BB + p0]  = b;
    g_gates[i0 * BB + p0] = inv;
    int p1 = atomicAdd(&g_counts[i1], 1);
    g_rows[i1 * BB + p1]  = b;
    g_gates[i1 * BB + p1] = ex * inv;
}

// per-expert scatter to padded slots; offsets via in-block 8-element prefix
__global__ void schedule_kernel() {
    int e = blockIdx.x;
    int off = 0, total = 0;
#pragma unroll
    for (int i = 0; i < EE; ++i) {
        int c = (g_counts[i] + 7) & ~7;
        if (i < e) off += c;
        total += c;
    }
    if (e == 0 && threadIdx.x == 0) g_total = total;
    int cnt = g_counts[e];
    int pad = (cnt + 7) & ~7;
    for (int j = threadIdx.x; j < pad; j += 256) {
        int slot = off + j;
        if (j < cnt) {
            int b = g_rows[e * BB + j];
            g_srow[slot]  = b;
            g_sgate[slot] = g_gates[e * BB + j];
            int pos = atomicAdd(&g_binc[b], 1);
            g_inv[b * 2 + pos] = slot;
        } else {
            g_srow[slot]  = g_rows[e * BB];
            g_sgate[slot] = 0.f;
        }
    }
    for (int t = threadIdx.x; t < pad / 8; t += 256) g_texp[off / 8 + t] = e;
}

__global__ void convw_kernel(const float* __restrict__ W1, const float* __restrict__ W2) {
    size_t n   = (size_t)EE * DD * FF;
    size_t idx = ((size_t)blockIdx.x * 256 + threadIdx.x) * 4;
    if (idx < n) {
        float4 v = *(const float4*)(W1 + idx);
        g_W1h[idx + 0] = __float2half_rn(v.x); g_W1h[idx + 1] = __float2half_rn(v.y);
        g_W1h[idx + 2] = __float2half_rn(v.z); g_W1h[idx + 3] = __float2half_rn(v.w);
    } else {
        size_t j = idx - n;
        if (j >= n) return;
        float4 v = *(const float4*)(W2 + j);
        g_W2h[j + 0] = __float2half_rn(v.x); g_W2h[j + 1] = __float2half_rn(v.y);
        g_W2h[j + 2] = __float2half_rn(v.z); g_W2h[j + 3] = __float2half_rn(v.w);
    }
}

__global__ void gather_kernel(const float* __restrict__ X) {
    int slot = blockIdx.x;
    if (slot >= g_total) return;
    int b = g_srow[slot];
    const float4* src = (const float4*)(X + (size_t)b * PP * DD);
    __half2* dst = (__half2*)(g_Xg + (size_t)slot * PP * DD);
    for (int i = threadIdx.x; i < PP * DD / 4; i += 256) {
        float4 v = src[i];
        dst[i * 2 + 0] = __floats2half2_rn(v.x, v.y);
        dst[i * 2 + 1] = __floats2half2_rn(v.z, v.w);
    }
}

// ---------------- GEMM pass 1: H = gelu(X @ W1 + b1), A-resident ----------------
// smem: A[128][520]h = 133120 B | B[2][64][136]h = 34816 B | C[128][68]f = 34816 B
#define LDA1 520
#define LDB  136
#define LDC  68
#define SM1_B 133120
#define SM1_C 167936
#define SM1_BYTES 202752

__global__ __launch_bounds__(256)
void gemm1_kernel(const float* __restrict__ bias) {
    int tile = blockIdx.x;
    if (tile * 8 >= g_total) return;
    int e = g_texp[tile];

    extern __shared__ char sm[];
    half*  A  = (half*)sm;
    half*  Bs = (half*)(sm + SM1_B);
    float* C  = (float*)(sm + SM1_C);
    uint32_t sA = smem_u32(A), sB = smem_u32(Bs);

    const half* Ag = g_Xg + (size_t)tile * 128 * DD;
    const half* Bg = g_W1h + (size_t)e * DD * FF;
    const float* be = bias + e * FF;

    int tid = threadIdx.x, wid = tid >> 5;
    int wm = (wid >> 1) * 32, wn = (wid & 1) * 64;

    // resident A: 128x512 fp16 = 8192 16B chunks
#pragma unroll
    for (int i = 0; i < 32; ++i) {
        int idx = i * 256 + tid;
        int r = idx >> 6, c = (idx & 63) << 3;
        cp16(sA + (uint32_t)(r * LDA1 + c) * 2, Ag + r * DD + c);
    }

    auto stageB = [&](int q) {
        uint32_t dst = sB + (uint32_t)(q & 1) * (64 * LDB * 2);
        int nb = (q >> 3) << 7, k0 = (q & 7) << 6;
#pragma unroll
        for (int i = 0; i < 4; ++i) {
            int idx = i * 256 + tid;
            int r = idx >> 4, c = (idx & 15) << 3;
            cp16(dst + (uint32_t)(r * LDB + c) * 2, Bg + (size_t)(k0 + r) * FF + nb + c);
        }
    };
    stageB(0);
    CP_COMMIT();

    wmma::fragment<wmma::accumulator, 16, 16, 16, float> acc[2][4];

    for (int q = 0; q < 128; ++q) {
        int kc = q & 7;
        if (kc == 0) {
#pragma unroll
            for (int i = 0; i < 2; ++i)
#pragma unroll
                for (int j = 0; j < 4; ++j) wmma::fill_fragment(acc[i][j], 0.f);
        }
        if (q + 1 < 128) { stageB(q + 1); CP_COMMIT(); CP_WAIT(1); }
        else             { CP_WAIT(0); }
        __syncthreads();

        half* Bq = Bs + (q & 1) * (64 * LDB);
        int k0 = kc << 6;
#pragma unroll
        for (int kk = 0; kk < 64; kk += 16) {
            wmma::fragment<wmma::matrix_a, 16, 16, 16, half, wmma::row_major> af[2];
            wmma::fragment<wmma::matrix_b, 16, 16, 16, half, wmma::row_major> bf[4];
            wmma::load_matrix_sync(af[0], A + (wm +  0) * LDA1 + k0 + kk, LDA1);
            wmma::load_matrix_sync(af[1], A + (wm + 16) * LDA1 + k0 + kk, LDA1);
#pragma unroll
            for (int j = 0; j < 4; ++j)
                wmma::load_matrix_sync(bf[j], Bq + kk * LDB + wn + 16 * j, LDB);
#pragma unroll
            for (int i = 0; i < 2; ++i)
#pragma unroll
                for (int j = 0; j < 4; ++j) wmma::mma_sync(acc[i][j], af[i], bf[j], acc[i][j]);
        }
        __syncthreads();   // compute done before next iter's stage overwrites B buf

        if (kc == 7) {
            int nb = (q >> 3) << 7;
#pragma unroll
            for (int p = 0; p < 2; ++p) {   // two N=64 phases through C
                if ((wid & 1) == p) {
#pragma unroll
                    for (int i = 0; i < 2; ++i)
#pragma unroll
                        for (int j = 0; j < 4; ++j)
                            wmma::store_matrix_sync(C + (wm + 16 * i) * LDC + 16 * j,
                                                    acc[i][j], LDC, wmma::mem_row_major);
                }
                __syncthreads();
                for (int i = tid; i < 128 * 64; i += 256) {
                    int m = i >> 6, n = i & 63;
                    float t = C[m * LDC + n] + be[nb + p * 64 + n];
                    g_H[(size_t)(tile * 128 + m) * FF + nb + p * 64 + n] =
                        __float2half_rn(gelu_t(t));
                }
                __syncthreads();
            }
        }
    }
}

// ---------------- GEMM pass 2: Y = gate*(H @ W2 + b2), fp16 out ----------------
// smem: A[2][128][72]h = 36864 B | B[2][64][136]h = 34816 B | C[128][68]f = 34816 B
#define LDA2 72
#define SM2_B 36864
#define SM2_C 71680
#define SM2_BYTES 106496

__global__ __launch_bounds__(256)
void gemm2_kernel(const float* __restrict__ bias) {
    int tile = blockIdx.y;                 // tile in y; 4 N-chunk CTAs x-adjacent
    if (tile * 8 >= g_total) return;
    int e  = g_texp[tile];
    int nb = blockIdx.x << 7;

    extern __shared__ char sm[];
    half*  As = (half*)sm;
    half*  Bs = (half*)(sm + SM2_B);
    float* C  = (float*)(sm + SM2_C);
    uint32_t sA = smem_u32(As), sB = smem_u32(Bs);

    const half* Ag = g_H  + (size_t)tile * 128 * FF;
    const half* Bg = g_W2h + (size_t)e * FF * DD;
    const float* be = bias + e * DD;

    int tid = threadIdx.x, wid = tid >> 5;
    int wm = (wid >> 1) * 32, wn = (wid & 1) * 64;

    auto stage = [&](int q) {
        int k0 = q << 6, buf = q & 1;
        uint32_t da = sA + (uint32_t)buf * (128 * LDA2 * 2);
        uint32_t db = sB + (uint32_t)buf * (64 * LDB * 2);
#pragma unroll
        for (int i = 0; i < 4; ++i) {
            int idx = i * 256 + tid;
            int r = idx >> 3, c = (idx & 7) << 3;
            cp16(da + (uint32_t)(r * LDA2 + c) * 2, Ag + (size_t)r * FF + k0 + c);
        }
#pragma unroll
        for (int i = 0; i < 4; ++i) {
            int idx = i * 256 + tid;
            int r = idx >> 4, c = (idx & 15) << 3;
            cp16(db + (uint32_t)(r * LDB + c) * 2, Bg + (size_t)(k0 + r) * DD + nb + c);
        }
    };
    stage(0);
    CP_COMMIT();

    wmma::fragment<wmma::accumulator, 16, 16, 16, float> acc[2][4];
#pragma unroll
    for (int i = 0; i < 2; ++i)
#pragma unroll
        for (int j = 0; j < 4; ++j) wmma::fill_fragment(acc[i][j], 0.f);

    for (int q = 0; q < 32; ++q) {
        if (q + 1 < 32) { stage(q + 1); CP_COMMIT(); CP_WAIT(1); }
        else            { CP_WAIT(0); }
        __syncthreads();

        half* Aq = As + (q & 1) * (128 * LDA2);
        half* Bq = Bs + (q & 1) * (64 * LDB);
#pragma unroll
        for (int kk = 0; kk < 64; kk += 16) {
            wmma::fragment<wmma::matrix_a, 16, 16, 16, half, wmma::row_major> af[2];
            wmma::fragment<wmma::matrix_b, 16, 16, 16, half, wmma::row_major> bf[4];
            wmma::load_matrix_sync(af[0], Aq + (wm +  0) * LDA2 + kk, LDA2);
            wmma::load_matrix_sync(af[1], Aq + (wm + 16) * LDA2 + kk, LDA2);
#pragma unroll
            for (int j = 0; j < 4; ++j)
                wmma::load_matrix_sync(bf[j], Bq + kk * LDB + wn + 16 * j, LDB);
#pragma unroll
            for (int i = 0; i < 2; ++i)
#pragma unroll
                for (int j = 0; j < 4; ++j) wmma::mma_sync(acc[i][j], af[i], bf[j], acc[i][j]);
        }
        __syncthreads();
    }

#pragma unroll
    for (int p = 0; p < 2; ++p) {
        if ((wid & 1) == p) {
#pragma unroll
            for (int i = 0; i < 2; ++i)
#pragma unroll
                for (int j = 0; j < 4; ++j)
                    wmma::store_matrix_sync(C + (wm + 16 * i) * LDC + 16 * j,
                                            acc[i][j], LDC, wmma::mem_row_major);
        }
        __syncthreads();
        for (int i = tid; i < 128 * 32; i += 256) {
            int m = i >> 5, n = (i & 31) * 2;
            int slot = tile * 8 + (m >> 4);
            float gt = g_sgate[slot];
            float y0 = (C[m * LDC + n]     + be[nb + p * 64 + n])     * gt;
            float y1 = (C[m * LDC + n + 1] + be[nb + p * 64 + n + 1]) * gt;
            *(__half2*)(g_Yh + (size_t)(tile * 128 + m) * DD + nb + p * 64 + n) =
                __floats2half2_rn(y0, y1);
        }
        __syncthreads();
    }
}

// out[b] = Y[slot0(b)] + Y[slot1(b)]  (fp16 reads, fp32 sum; commutative)
__global__ void combine_kernel(float* __restrict__ out) {
    int b  = blockIdx.x;
    int s0 = g_inv[2 * b], s1 = g_inv[2 * b + 1];
    const uint4* y0 = (const uint4*)(g_Yh + (size_t)s0 * PP * DD);
    const uint4* y1 = (const uint4*)(g_Yh + (size_t)s1 * PP * DD);
    float4* o = (float4*)(out + (size_t)b * PP * DD);
    for (int i = threadIdx.x; i < PP * DD / 8; i += 256) {
        uint4 a = y0[i], c = y1[i];
        __half2 a0 = *(__half2*)&a.x, a1 = *(__half2*)&a.y, a2 = *(__half2*)&a.z, a3 = *(__half2*)&a.w;
        __half2 c0 = *(__half2*)&c.x, c1 = *(__half2*)&c.y, c2 = *(__half2*)&c.z, c3 = *(__half2*)&c.w;
        float2 f0 = __half22float2(a0), g0 = __half22float2(c0);
        float2 f1 = __half22float2(a1), g1 = __half22float2(c1);
        float2 f2 = __half22float2(a2), g2 = __half22float2(c2);
        float2 f3 = __half22float2(a3), g3 = __half22float2(c3);
        o[i * 2 + 0] = make_float4(f0.x + g0.x, f0.y + g0.y, f1.x + g1.x, f1.y + g1.y);
        o[i * 2 + 1] = make_float4(f2.x + g2.x, f2.y + g2.y, f3.x + g3.x, f3.y + g3.y);
    }
}

// ---------------- launch ----------------
extern "C" void kernel_launch(void* const* d_in, const int* in_sizes, int n_in,
                              void* d_out, int out_size) {
    const float* patch_x  = (const float*)d_in[0];
    const float* affinity = (const float*)d_in[2];
    const float* noise    = (const float*)d_in[3];
    const float* W1       = (const float*)d_in[4];
    const float* b1       = (const float*)d_in[5];
    const float* W2       = (const float*)d_in[6];
    const float* b2       = (const float*)d_in[7];
    float* out = (float*)d_out;

    zero_kernel<<<16, 256>>>();
    router_kernel<<<BB / 256, 256>>>(affinity, noise);
    schedule_kernel<<<EE, 256>>>();

    size_t wn = (size_t)EE * DD * FF;
    int convBlocks = (int)((2 * wn / 4 + 255) / 256);
    convw_kernel<<<convBlocks, 256>>>(W1, W2);
    gather_kernel<<<MAXSLOTS, 256>>>(patch_x);

    cudaFuncSetAttribute(gemm1_kernel,
                         cudaFuncAttributeMaxDynamicSharedMemorySize, SM1_BYTES);
    cudaFuncSetAttribute(gemm2_kernel,
                         cudaFuncAttributeMaxDynamicSharedMemorySize, SM2_BYTES);

    gemm1_kernel<<<MAXTILES, 256, SM1_BYTES>>>(b1);
    dim3 g2(DD / 128, MAXTILES);
    gemm2_kernel<<<g2, 256, SM2_BYTES>>>(b2);

    combine_kernel<<<BB, 256>>>(out);
}